// round 8
// baseline (speedup 1.0000x reference)
#include <cuda_runtime.h>
#include <math_constants.h>

// Morphological opening: dilate3x3(erode3x3(x)), flat SE, geodesic SAME padding.
// x: (16,3,1024,1024) f32 -> 48 planes of 1024x1024.
//
// Fused, smem-free, register-pipelined, overlapped-tile, ROW-PAIR version:
//   - warp loads 128 cols (lane l holds cols 4l..4l+3 as float4), owns 124 valid
//     output cols; tiles stride by 124 (9 x-tiles, last anchored at 896)
//   - horizontal min3/max3 via warp shuffles; interior edge lanes masked at store
//   - vertical pad via clamp-to-edge row replication (identity for min windows);
//     dilation -inf pad handled explicitly on the two image-boundary g rows
//   - TWO output rows per iteration with shared vertical algebra:
//       m  = min(hB,hC);  e1 = min(hA,m);   e2 = min(m,hD)
//       t  = max(gB,g1);  o0 = max(gA,t);   o1 = max(t,g2)
//     -> ~18% fewer instructions/row, 2 LDGs issued back-to-back per iteration
//   - TH=32 -> 6912 blocks of 64 thr at 16 blk/SM = 2.92 waves (tail ~3%)

#define TH      32
#define IMG_W   1024
#define IMG_H   1024
#define PLANES  48
#define TILES_X 9
#define TILE_STRIDE 124
#define TILES_Y (IMG_H / TH)    // 32

__device__ __forceinline__ float min3f(float a, float b, float c) {
    return fminf(a, fminf(b, c));
}
__device__ __forceinline__ float max3f(float a, float b, float c) {
    return fmaxf(a, fmaxf(b, c));
}

__global__ void __launch_bounds__(64, 16)
morph_open_kernel(const float* __restrict__ in, float* __restrict__ out) {
    const unsigned FULL = 0xffffffffu;
    const float INF  = CUDART_INF_F;
    const float NINF = -CUDART_INF_F;

    const int warp_g = blockIdx.x * 2 + (threadIdx.x >> 5);
    const int lane   = threadIdx.x & 31;

    const int tx = warp_g % TILES_X;
    const int ty = (warp_g / TILES_X) % TILES_Y;
    const int p  = warp_g / (TILES_X * TILES_Y);
    if (p >= PLANES) return;

    const float* __restrict__ base  = in  + (size_t)p * (IMG_W * IMG_H);
    float*       __restrict__ obase = out + (size_t)p * (IMG_W * IMG_H);

    // tile anchors: 0,124,...,868, then 896 (last tile right-aligned)
    const int x0 = (tx == TILES_X - 1) ? (IMG_W - 128) : tx * TILE_STRIDE;
    const int y0 = ty * TH;
    const int cbase = x0 + 4 * lane;
    const bool leftEdge  = (tx == 0);
    const bool rightEdge = (tx == TILES_X - 1);
    const bool isL = (lane == 0);
    const bool isR = (lane == 31);
    const bool storeFull = (!isL || leftEdge) && (!isR || rightEdge);

    // ---- row loader: UNCONDITIONAL, clamp-to-edge (identity for min/max pad)
    auto loadrow = [&](int r, float4& x4) {
        int rc = min(max(r, 0), IMG_H - 1);
        x4 = *reinterpret_cast<const float4*>(base + (size_t)rc * IMG_W + cbase);
    };

    // ---- horizontal min3 of one input row (shuffle-only)
    auto hminrow = [&](const float4& x, float4& h) {
        float xl = __shfl_up_sync(FULL, x.w, 1);
        if (isL) xl = INF;
        float xr = __shfl_down_sync(FULL, x.x, 1);
        if (isR) xr = INF;
        h.x = min3f(xl,  x.x, x.y);
        h.y = min3f(x.x, x.y, x.z);
        h.z = min3f(x.y, x.z, x.w);
        h.w = min3f(x.z, x.w, xr);
    };

    // ---- horizontal max3 of an erosion row (shuffle-only)
    auto hmaxrow = [&](const float4& e, float4& g) {
        float el = __shfl_up_sync(FULL, e.w, 1);
        if (isL) el = NINF;
        float er = __shfl_down_sync(FULL, e.x, 1);
        if (isR) er = NINF;
        g.x = max3f(el,  e.x, e.y);
        g.y = max3f(e.x, e.y, e.z);
        g.z = max3f(e.y, e.z, e.w);
        g.w = max3f(e.z, e.w, er);
    };

    auto vmin = [&](const float4& a, const float4& b, const float4& c, float4& o) {
        o.x = min3f(a.x, b.x, c.x);
        o.y = min3f(a.y, b.y, c.y);
        o.z = min3f(a.z, b.z, c.z);
        o.w = min3f(a.w, b.w, c.w);
    };
    auto vmin2 = [&](const float4& a, const float4& b, float4& o) {
        o.x = fminf(a.x, b.x); o.y = fminf(a.y, b.y);
        o.z = fminf(a.z, b.z); o.w = fminf(a.w, b.w);
    };
    auto vmax2 = [&](const float4& a, const float4& b, float4& o) {
        o.x = fmaxf(a.x, b.x); o.y = fmaxf(a.y, b.y);
        o.z = fmaxf(a.z, b.z); o.w = fmaxf(a.w, b.w);
    };

    // ---- prologue: front-batch 6 loads: rows y0-2..y0+1 (for h) + y0+2,y0+3 (pair buf)
    float4 t_m2, t_m1, t_0, t_1, p0, p1;
    loadrow(y0 - 2, t_m2);
    loadrow(y0 - 1, t_m1);
    loadrow(y0,     t_0);
    loadrow(y0 + 1, t_1);
    loadrow(y0 + 2, p0);
    loadrow(y0 + 3, p1);

    float4 h_m2, h_m1, hA, hB;
    hminrow(t_m2, h_m2);
    hminrow(t_m1, h_m1);
    hminrow(t_0,  hA);      // h(y0)
    hminrow(t_1,  hB);      // h(y0+1)

    // gA = g(y0-1): -inf at image top (erosion rows outside image are -inf for dilation)
    float4 gA, gB;
    if (y0 == 0) {
        gA = make_float4(NINF, NINF, NINF, NINF);
    } else {
        float4 e;
        vmin(h_m2, h_m1, hA, e);   // e(y0-1)
        hmaxrow(e, gA);
    }
    {
        float4 e;
        vmin(h_m1, hA, hB, e);     // e(y0) — always in-image
        hmaxrow(e, gB);
    }

    #pragma unroll 4
    for (int k = 0; k < TH / 2; ++k) {
        const int r0 = y0 + 2 * k;

        // hmin of the buffered pair (rows r0+2, r0+3)
        float4 hC, hD;
        hminrow(p0, hC);
        hminrow(p1, hD);

        // prefetch next pair (rows r0+4, r0+5) — issued back-to-back
        loadrow(r0 + 4, p0);
        loadrow(r0 + 5, p1);

        // erosion rows r0+1, r0+2 with shared middle min
        float4 m, e1, e2;
        vmin2(hB, hC, m);
        vmin2(hA, m, e1);          // e(r0+1)
        vmin2(m, hD, e2);          // e(r0+2)

        // g(r0+1): always interior (r0+1 in [y0+1, y0+31])
        float4 g1, g2;
        hmaxrow(e1, g1);
        // g(r0+2): out-of-image only at the very bottom tile's last pair
        if ((unsigned)(r0 + 2) < (unsigned)IMG_H) {
            hmaxrow(e2, g2);
        } else {
            g2 = make_float4(NINF, NINF, NINF, NINF);
        }

        // outputs rows r0, r0+1 with shared middle max
        float4 t, o0, o1;
        vmax2(gB, g1, t);
        vmax2(gA, t, o0);          // o(r0)   = max(g(r0-1), g(r0), g(r0+1))
        vmax2(t, g2, o1);          // o(r0+1) = max(g(r0), g(r0+1), g(r0+2))

        float* orow0 = obase + (size_t)r0 * IMG_W + cbase;
        float* orow1 = orow0 + IMG_W;
        if (storeFull) {
            __stcs(reinterpret_cast<float4*>(orow0), o0);
            __stcs(reinterpret_cast<float4*>(orow1), o1);
        } else if (isL) {
            __stcs(reinterpret_cast<float2*>(orow0 + 2), make_float2(o0.z, o0.w));
            __stcs(reinterpret_cast<float2*>(orow1 + 2), make_float2(o1.z, o1.w));
        } else { // isR, interior
            __stcs(reinterpret_cast<float2*>(orow0), make_float2(o0.x, o0.y));
            __stcs(reinterpret_cast<float2*>(orow1), make_float2(o1.x, o1.y));
        }

        // rotate rings
        hA = hC; hB = hD;
        gA = g1; gB = g2;
    }
}

extern "C" void kernel_launch(void* const* d_in, const int* in_sizes, int n_in,
                              void* d_out, int out_size) {
    const float* x = (const float*)d_in[0];
    float* o = (float*)d_out;
    // 48 planes * 32 y-tiles * 9 x-tiles = 13824 warps; 64-thread blocks (2 warps)
    const int total_warps = PLANES * TILES_Y * TILES_X;
    const int blocks = (total_warps * 32 + 63) / 64;   // 6912
    morph_open_kernel<<<blocks, 64>>>(x, o);
}